// round 14
// baseline (speedup 1.0000x reference)
#include <cuda_runtime.h>
#include <cuda_bf16.h>
#include <stdint.h>

// ============================================================================
// Problem dims
// ============================================================================
#define M_DIM 8192       // 4 * 2048 tokens
#define K_DIM 4096       // in_features
#define N_DIM 16384      // out_features

// GEMM tiling (bf16 path) — 2 CTAs/SM
#define BM 128
#define BN 128
#define BK 64                          // bf16 K elements per chunk = 128 B/row
#define NKC (K_DIM / BK)               // 64 chunks
#define STAGES 3
#define ROWB 128                       // bytes per SMEM row
#define STAGE_BYTES ((BM + BN) * ROWB) // 32768
#define GEMM_SMEM (STAGES * STAGE_BYTES) // 98304 -> 2 CTAs per SM
#define K_BYTES (K_DIM * 2)            // global row stride in bytes
#define GTHREADS 256

// ============================================================================
// Scratch (static device memory — no allocations allowed)
// ============================================================================
__device__ __align__(128) __nv_bfloat16 g_xq[(size_t)M_DIM * K_DIM]; // 64 MB
__device__ __align__(128) __nv_bfloat16 g_wt[(size_t)N_DIM * K_DIM]; // 128 MB
__device__ float  g_sx[M_DIM];
__device__ double g_partial[2048];
__device__ float  g_wscale;
__device__ unsigned int g_ctr = 0;

// ============================================================================
// PTX helpers (base sm ISA only — no tcgen05)
// ============================================================================
__device__ __forceinline__ uint32_t smem_u32(const void* p) {
    uint32_t a;
    asm("{ .reg .u64 t; cvta.to.shared.u64 t, %1; cvt.u32.u64 %0, t; }" : "=r"(a) : "l"(p));
    return a;
}
__device__ __forceinline__ void cp16(uint32_t dst, const void* src) {
    asm volatile("cp.async.cg.shared.global [%0], [%1], 16;\n" :: "r"(dst), "l"(src) : "memory");
}
__device__ __forceinline__ void cp_commit() { asm volatile("cp.async.commit_group;" ::: "memory"); }
__device__ __forceinline__ void cp_wait1()  { asm volatile("cp.async.wait_group 1;" ::: "memory"); }
__device__ __forceinline__ void cp_wait0()  { asm volatile("cp.async.wait_group 0;" ::: "memory"); }

__device__ __forceinline__ void ldm_x4(uint32_t* r, uint32_t addr) {
    asm volatile("ldmatrix.sync.aligned.m8n8.x4.shared.b16 {%0,%1,%2,%3}, [%4];"
                 : "=r"(r[0]), "=r"(r[1]), "=r"(r[2]), "=r"(r[3]) : "r"(addr));
}
// bf16 HMMA with fp32 accumulation — the only hardware tensor path reachable
// from the plain-sm_103 harness target (int8 and fp8 legacy mma are emulated).
__device__ __forceinline__ void hmma(float* c, const uint32_t* a, const uint32_t* b) {
    asm volatile("mma.sync.aligned.m16n8k16.row.col.f32.bf16.bf16.f32 "
                 "{%0,%1,%2,%3}, {%4,%5,%6,%7}, {%8,%9}, {%0,%1,%2,%3};"
                 : "+f"(c[0]), "+f"(c[1]), "+f"(c[2]), "+f"(c[3])
                 : "r"(a[0]), "r"(a[1]), "r"(a[2]), "r"(a[3]), "r"(b[0]), "r"(b[1]));
}
// Streaming store: output written once, never re-read — evict-first.
__device__ __forceinline__ void stg_cs_v2(float* p, float x, float y) {
    asm volatile("st.global.cs.v2.f32 [%0], {%1, %2};" :: "l"(p), "f"(x), "f"(y) : "memory");
}

// SW128 swizzle: 16B granule offset c (bits 4-6) XORed with (row&7)<<4.
// k-step offsets compose by XOR (k bits live inside the swizzled field).
__device__ __forceinline__ uint32_t swz(int row, int c) {
    return (uint32_t)(row * ROWB + (c ^ ((row & 7) << 4)));
}

// ============================================================================
// Kernel 1: |w| mean via partial sums + deterministic last-block reduce.
// ============================================================================
__global__ void k_wabs(const float* __restrict__ w) {
    int tid = threadIdx.x;
    const float4* wp = reinterpret_cast<const float4*>(w) + (size_t)blockIdx.x * 8192;
    float ssum = 0.f;
#pragma unroll
    for (int i = 0; i < 32; i++) {
        float4 v = wp[tid + i * 256];
        ssum += fabsf(v.x) + fabsf(v.y) + fabsf(v.z) + fabsf(v.w);
    }
#pragma unroll
    for (int o = 16; o > 0; o >>= 1) ssum += __shfl_xor_sync(0xffffffffu, ssum, o);
    __shared__ double wsum[8];
    __shared__ int is_last;
    if ((tid & 31) == 0) wsum[tid >> 5] = (double)ssum;
    __syncthreads();
    if (tid == 0) {
        double t = 0.0;
#pragma unroll
        for (int i = 0; i < 8; i++) t += wsum[i];
        g_partial[blockIdx.x] = t;
        __threadfence();
        unsigned int prev = atomicAdd(&g_ctr, 1u);
        is_last = (prev == gridDim.x - 1);
    }
    __syncthreads();
    if (!is_last) return;
    __threadfence();
    double t = 0.0;
#pragma unroll
    for (int i = 0; i < 8; i++) t += g_partial[tid + i * 256];
    __shared__ double sm[256];
    sm[tid] = t;
    __syncthreads();
    if (tid == 0) {
        double a = 0.0;
        for (int i = 0; i < 256; i++) a += sm[i];
        float mean = (float)(a / 67108864.0);
        g_wscale = fmaxf(mean, 1e-5f);
        g_ctr = 0;  // reset for next graph replay
    }
}

// Kernel 2: ternarize weights -> bf16 {-1,0,+1}. grid 16384 x 256.
__global__ void k_wquant(const float* __restrict__ w) {
    float half = 0.5f * g_wscale;
    size_t base = (size_t)blockIdx.x * 1024 + threadIdx.x; // float4 units
    const float4* wp = reinterpret_cast<const float4*>(w);
    uint2* o = reinterpret_cast<uint2*>(g_wt);
#pragma unroll
    for (int i = 0; i < 4; i++) {
        size_t idx = base + (size_t)i * 256;
        float4 v = wp[idx];
        // ternary bf16 bits: +1 = 0x3F80, -1 = 0xBF80, 0 = 0
        uint32_t a = (v.x > half) ? 0x3F80u : ((v.x < -half) ? 0xBF80u : 0u);
        uint32_t b = (v.y > half) ? 0x3F80u : ((v.y < -half) ? 0xBF80u : 0u);
        uint32_t c = (v.z > half) ? 0x3F80u : ((v.z < -half) ? 0xBF80u : 0u);
        uint32_t d = (v.w > half) ? 0x3F80u : ((v.w < -half) ? 0xBF80u : 0u);
        o[idx] = make_uint2(a | (b << 16), c | (d << 16));
    }
}

// Kernel 3: per-token int4 quant of x -> bf16 ints + s[token]. grid 8192 x 128.
__global__ void k_xquant(const float* __restrict__ x) {
    int token = blockIdx.x;
    int tid = threadIdx.x;
    const float4* xin = reinterpret_cast<const float4*>(x + (size_t)token * K_DIM);
    float4 v[8];
    float amax = 0.f;
#pragma unroll
    for (int i = 0; i < 8; i++) {
        v[i] = xin[tid + i * 128];
        amax = fmaxf(amax, fmaxf(fmaxf(fabsf(v[i].x), fabsf(v[i].y)),
                                 fmaxf(fabsf(v[i].z), fabsf(v[i].w))));
    }
#pragma unroll
    for (int o = 16; o > 0; o >>= 1) amax = fmaxf(amax, __shfl_xor_sync(0xffffffffu, amax, o));
    __shared__ float wmax[4];
    if ((tid & 31) == 0) wmax[tid >> 5] = amax;
    __syncthreads();
    amax = fmaxf(fmaxf(wmax[0], wmax[1]), fmaxf(wmax[2], wmax[3]));
    float s = __fdiv_rn(fmaxf(amax, 1e-5f), 7.0f);
    float inv = __fdiv_rn(1.0f, s);
    if (tid == 0) g_sx[token] = s;
    uint2* qo = reinterpret_cast<uint2*>(g_xq + (size_t)token * K_DIM);
#pragma unroll
    for (int i = 0; i < 8; i++) {
        float a = fminf(fmaxf(rintf(v[i].x * inv), -8.f), 7.f);
        float b = fminf(fmaxf(rintf(v[i].y * inv), -8.f), 7.f);
        float c = fminf(fmaxf(rintf(v[i].z * inv), -8.f), 7.f);
        float d = fminf(fmaxf(rintf(v[i].w * inv), -8.f), 7.f);
        // small integers are exact in bf16
        uint32_t ab = ((uint32_t)__bfloat16_as_ushort(__float2bfloat16(a)))
                    | ((uint32_t)__bfloat16_as_ushort(__float2bfloat16(b)) << 16);
        uint32_t cd = ((uint32_t)__bfloat16_as_ushort(__float2bfloat16(c)))
                    | ((uint32_t)__bfloat16_as_ushort(__float2bfloat16(d)) << 16);
        qo[tid + i * 128] = make_uint2(ab, cd);
    }
}

// ============================================================================
// Kernel 4: bf16 HMMA GEMM. BM=128 x BN=128 x BK=64, 3-stage cp.async,
// 8 warps of 64x32, 2 CTAs per SM. ks=0 fragment loads peeled AHEAD of the
// cp.async refill (single fragment set — registers unchanged vs the 83% base).
// ============================================================================
__device__ __forceinline__ void load_chunk(uint32_t stage, const __nv_bfloat16* Abase,
                                           const __nv_bfloat16* Bbase, int kc, int tid) {
    uint32_t a_s = stage;
    uint32_t b_s = stage + BM * ROWB;
    const char* ag = reinterpret_cast<const char*>(Abase) + kc * ROWB;
    const char* bg = reinterpret_cast<const char*>(Bbase) + kc * ROWB;
#pragma unroll
    for (int i = 0; i < 4; i++) {
        int g = tid + GTHREADS * i;
        int r = g >> 3, c = (g & 7) * 16;
        cp16(a_s + swz(r, c), ag + (size_t)r * K_BYTES + c);
    }
#pragma unroll
    for (int i = 0; i < 4; i++) {
        int g = tid + GTHREADS * i;
        int r = g >> 3, c = (g & 7) * 16;
        cp16(b_s + swz(r, c), bg + (size_t)r * K_BYTES + c);
    }
    cp_commit();
}

__global__ void __launch_bounds__(GTHREADS, 2) k_gemm(float* __restrict__ out) {
    extern __shared__ char smem[];
    uint32_t sb = smem_u32(smem);
    int tid = threadIdx.x;
    int wid = tid >> 5;
    int lane = tid & 31;

    // Grouped rasterization for L2 reuse
    const int num_pid_n = N_DIM / BN; // 128
    const int GROUP = 8;
    int pid = blockIdx.x;
    int npg = GROUP * num_pid_n;
    int group_id = pid / npg;
    int first_m = group_id * GROUP;
    int pid_m = first_m + ((pid % npg) % GROUP);
    int pid_n = (pid % npg) / GROUP;

    const __nv_bfloat16* Abase = g_xq + (size_t)pid_m * BM * K_DIM;
    const __nv_bfloat16* Bbase = g_wt + (size_t)pid_n * BN * K_DIM;

    int WM = (wid & 1) * 64;   // warp m offset (0 or 64)
    int WN = (wid >> 1) * 32;  // warp n offset (0,32,64,96)

    float acc[4][4][4];
#pragma unroll
    for (int i = 0; i < 4; i++)
#pragma unroll
        for (int j = 0; j < 4; j++)
#pragma unroll
            for (int q = 0; q < 4; q++) acc[i][j][q] = 0.f;

    // ldmatrix base offsets (k-step selects bits 5-6 by XOR)
    uint32_t a_off[4];
#pragma unroll
    for (int i = 0; i < 4; i++) {
        int row = WM + 16 * i + (lane & 15);
        a_off[i] = swz(row, ((lane >> 4) & 1) * 16);
    }
    uint32_t b_off[2];
#pragma unroll
    for (int p = 0; p < 2; p++) {
        int n = WN + 16 * p + (lane & 7) + ((lane >> 4) & 1) * 8;
        b_off[p] = (uint32_t)(BM * ROWB) + swz(n, ((lane >> 3) & 1) * 16);
    }

    // Prologue: fill 2 of 3 stages
    load_chunk(sb + 0 * STAGE_BYTES, Abase, Bbase, 0, tid);
    load_chunk(sb + 1 * STAGE_BYTES, Abase, Bbase, 1, tid);

    int slot = 0, lslot = 2;
#pragma unroll 1
    for (int kc = 0; kc < NKC; kc++) {
        if (kc < NKC - 1) cp_wait1(); else cp_wait0();
        __syncthreads();
        uint32_t stage = sb + slot * STAGE_BYTES;
        slot++; if (slot == STAGES) slot = 0;

        uint32_t ua[4][4], ub[2][4];
        // Peel: critical-path ks=0 fragment loads issue FIRST ...
#pragma unroll
        for (int i = 0; i < 4; i++) ldm_x4(ua[i], stage + a_off[i]);
#pragma unroll
        for (int p = 0; p < 2; p++) ldm_x4(ub[p], stage + b_off[p]);

        // ... then the refill for the freed slot (issue hides under LDSM lat).
        if (kc + 2 < NKC) {
            load_chunk(sb + lslot * STAGE_BYTES, Abase, Bbase, kc + 2, tid);
            lslot++; if (lslot == STAGES) lslot = 0;
        }

        // ks=0 MMA on the peeled fragments
#pragma unroll
        for (int p = 0; p < 2; p++)
#pragma unroll
            for (int i = 0; i < 4; i++) {
                hmma(acc[i][2 * p],     ua[i], ub[p]);
                hmma(acc[i][2 * p + 1], ua[i], ub[p] + 2);
            }
        // ks=1..3: same single fragment set, same schedule as the 83% base
#pragma unroll
        for (int ks = 1; ks < 4; ks++) {
            uint32_t kx = (uint32_t)(ks * 32);
#pragma unroll
            for (int i = 0; i < 4; i++) ldm_x4(ua[i], stage + (a_off[i] ^ kx));
#pragma unroll
            for (int p = 0; p < 2; p++) ldm_x4(ub[p], stage + (b_off[p] ^ kx));
#pragma unroll
            for (int p = 0; p < 2; p++)
#pragma unroll
                for (int i = 0; i < 4; i++) {
                    hmma(acc[i][2 * p],     ua[i], ub[p]);
                    hmma(acc[i][2 * p + 1], ua[i], ub[p] + 2);
                }
        }
    }

    // Epilogue: scale by s[m]*wscale, streaming stores (evict-first)
    float ws = g_wscale;
#pragma unroll
    for (int i = 0; i < 4; i++) {
        int row0 = pid_m * BM + WM + 16 * i + (lane >> 2);
        float s0 = g_sx[row0] * ws;
        float s1 = g_sx[row0 + 8] * ws;
        float* r0 = out + (size_t)row0 * N_DIM + pid_n * BN + WN;
        float* r1 = r0 + (size_t)8 * N_DIM;
#pragma unroll
        for (int j = 0; j < 4; j++) {
            int col = 8 * j + 2 * (lane & 3);
            stg_cs_v2(r0 + col, acc[i][j][0] * s0, acc[i][j][1] * s0);
            stg_cs_v2(r1 + col, acc[i][j][2] * s1, acc[i][j][3] * s1);
        }
    }
}

// ============================================================================
// Launch
// ============================================================================
extern "C" void kernel_launch(void* const* d_in, const int* in_sizes, int n_in,
                              void* d_out, int out_size) {
    const float* x = (const float*)d_in[0];
    const float* w = (const float*)d_in[1];
    if (n_in >= 2 && in_sizes[0] == 67108864) { // defensive: identify by size
        w = (const float*)d_in[0];
        x = (const float*)d_in[1];
    }
    float* out = (float*)d_out;

    cudaFuncSetAttribute(k_gemm, cudaFuncAttributeMaxDynamicSharedMemorySize, GEMM_SMEM);

    k_wabs<<<2048, 256>>>(w);        // includes deterministic final reduce
    k_wquant<<<16384, 256>>>(w);
    k_xquant<<<M_DIM, 128>>>(x);
    k_gemm<<<(M_DIM / BM) * (N_DIM / BN), GTHREADS, GEMM_SMEM>>>(out);
}

// round 15
// speedup vs baseline: 1.6926x; 1.6926x over previous
#include <cuda_runtime.h>
#include <cuda_bf16.h>
#include <stdint.h>

// ============================================================================
// Problem dims
// ============================================================================
#define M_DIM 8192       // 4 * 2048 tokens
#define K_DIM 4096       // in_features
#define N_DIM 16384      // out_features

// GEMM tiling (bf16 path) — 2 CTAs/SM
#define BM 128
#define BN 128
#define BK 64                          // bf16 K elements per chunk = 128 B/row
#define NKC (K_DIM / BK)               // 64 chunks
#define STAGES 3
#define ROWB 128                       // bytes per SMEM row
#define STAGE_BYTES ((BM + BN) * ROWB) // 32768
#define GEMM_SMEM (STAGES * STAGE_BYTES) // 98304 -> 2 CTAs per SM
#define K_BYTES (K_DIM * 2)            // global row stride in bytes
#define GTHREADS 256

#define WABS_BLOCKS 2048               // blocks doing |w| partial sums

// ============================================================================
// Scratch (static device memory — no allocations allowed)
// ============================================================================
__device__ __align__(128) __nv_bfloat16 g_xq[(size_t)M_DIM * K_DIM]; // 64 MB
__device__ __align__(128) __nv_bfloat16 g_wt[(size_t)N_DIM * K_DIM]; // 128 MB
__device__ float  g_sx[M_DIM];
__device__ double g_partial[2048];
__device__ float  g_wscale;
__device__ unsigned int g_ctr = 0;

// ============================================================================
// PTX helpers (base sm ISA only — no tcgen05)
// ============================================================================
__device__ __forceinline__ uint32_t smem_u32(const void* p) {
    uint32_t a;
    asm("{ .reg .u64 t; cvta.to.shared.u64 t, %1; cvt.u32.u64 %0, t; }" : "=r"(a) : "l"(p));
    return a;
}
__device__ __forceinline__ void cp16(uint32_t dst, const void* src) {
    asm volatile("cp.async.cg.shared.global [%0], [%1], 16;\n" :: "r"(dst), "l"(src) : "memory");
}
__device__ __forceinline__ void cp_commit() { asm volatile("cp.async.commit_group;" ::: "memory"); }
__device__ __forceinline__ void cp_wait1()  { asm volatile("cp.async.wait_group 1;" ::: "memory"); }
__device__ __forceinline__ void cp_wait0()  { asm volatile("cp.async.wait_group 0;" ::: "memory"); }

__device__ __forceinline__ void ldm_x4(uint32_t* r, uint32_t addr) {
    asm volatile("ldmatrix.sync.aligned.m8n8.x4.shared.b16 {%0,%1,%2,%3}, [%4];"
                 : "=r"(r[0]), "=r"(r[1]), "=r"(r[2]), "=r"(r[3]) : "r"(addr));
}
// bf16 HMMA with fp32 accumulation — the only hardware tensor path reachable
// from the plain-sm_103 harness target (int8 and fp8 legacy mma are emulated).
__device__ __forceinline__ void hmma(float* c, const uint32_t* a, const uint32_t* b) {
    asm volatile("mma.sync.aligned.m16n8k16.row.col.f32.bf16.bf16.f32 "
                 "{%0,%1,%2,%3}, {%4,%5,%6,%7}, {%8,%9}, {%0,%1,%2,%3};"
                 : "+f"(c[0]), "+f"(c[1]), "+f"(c[2]), "+f"(c[3])
                 : "r"(a[0]), "r"(a[1]), "r"(a[2]), "r"(a[3]), "r"(b[0]), "r"(b[1]));
}
// Streaming store: output written once, never re-read — evict-first.
__device__ __forceinline__ void stg_cs_v2(float* p, float x, float y) {
    asm volatile("st.global.cs.v2.f32 [%0], {%1, %2};" :: "l"(p), "f"(x), "f"(y) : "memory");
}

// SW128 swizzle: 16B granule offset c (bits 4-6) XORed with (row&7)<<4.
// k-step offsets compose by XOR (k bits live inside the swizzled field).
__device__ __forceinline__ uint32_t swz(int row, int c) {
    return (uint32_t)(row * ROWB + (c ^ ((row & 7) << 4)));
}

// ============================================================================
// Kernel 1 (FUSED): blocks [0, 2048)  -> |w| partial sums + deterministic
//                                        last-block reduce (counter vs 2048)
//                   blocks [2048, ..) -> per-token int4 quant of x (1 token
//                                        per block, 256 threads)
// The x-quant work is independent of w and hides inside this kernel's runtime.
// ============================================================================
__global__ void k_wabs_xq(const float* __restrict__ w, const float* __restrict__ x) {
    int tid = threadIdx.x;

    if (blockIdx.x < WABS_BLOCKS) {
        // ---- |w| partial sums (identical math/order to the validated version)
        const float4* wp = reinterpret_cast<const float4*>(w) + (size_t)blockIdx.x * 8192;
        float ssum = 0.f;
#pragma unroll
        for (int i = 0; i < 32; i++) {
            float4 v = wp[tid + i * 256];
            ssum += fabsf(v.x) + fabsf(v.y) + fabsf(v.z) + fabsf(v.w);
        }
#pragma unroll
        for (int o = 16; o > 0; o >>= 1) ssum += __shfl_xor_sync(0xffffffffu, ssum, o);
        __shared__ double wsum[8];
        __shared__ int is_last;
        if ((tid & 31) == 0) wsum[tid >> 5] = (double)ssum;
        __syncthreads();
        if (tid == 0) {
            double t = 0.0;
#pragma unroll
            for (int i = 0; i < 8; i++) t += wsum[i];
            g_partial[blockIdx.x] = t;
            __threadfence();
            unsigned int prev = atomicAdd(&g_ctr, 1u);
            is_last = (prev == WABS_BLOCKS - 1);
        }
        __syncthreads();
        if (!is_last) return;
        // Last wabs block: deterministic fixed-order reduction of 2048 partials.
        __threadfence();
        double t = 0.0;
#pragma unroll
        for (int i = 0; i < 8; i++) t += g_partial[tid + i * 256];
        __shared__ double sm[256];
        sm[tid] = t;
        __syncthreads();
        if (tid == 0) {
            double a = 0.0;
            for (int i = 0; i < 256; i++) a += sm[i];
            float mean = (float)(a / 67108864.0);
            g_wscale = fmaxf(mean, 1e-5f);
            g_ctr = 0;  // reset for next graph replay
        }
    } else {
        // ---- per-token x quant (256 threads per token, 4 float4 each)
        int token = blockIdx.x - WABS_BLOCKS;
        const float4* xin = reinterpret_cast<const float4*>(x + (size_t)token * K_DIM);
        float4 v[4];
        float amax = 0.f;
#pragma unroll
        for (int i = 0; i < 4; i++) {
            v[i] = xin[tid + i * 256];
            amax = fmaxf(amax, fmaxf(fmaxf(fabsf(v[i].x), fabsf(v[i].y)),
                                     fmaxf(fabsf(v[i].z), fabsf(v[i].w))));
        }
#pragma unroll
        for (int o = 16; o > 0; o >>= 1) amax = fmaxf(amax, __shfl_xor_sync(0xffffffffu, amax, o));
        __shared__ float wmax[8];
        if ((tid & 31) == 0) wmax[tid >> 5] = amax;
        __syncthreads();
        amax = wmax[0];
#pragma unroll
        for (int i = 1; i < 8; i++) amax = fmaxf(amax, wmax[i]);
        float s = __fdiv_rn(fmaxf(amax, 1e-5f), 7.0f);
        float inv = __fdiv_rn(1.0f, s);
        if (tid == 0) g_sx[token] = s;
        uint2* qo = reinterpret_cast<uint2*>(g_xq + (size_t)token * K_DIM);
#pragma unroll
        for (int i = 0; i < 4; i++) {
            float a = fminf(fmaxf(rintf(v[i].x * inv), -8.f), 7.f);
            float b = fminf(fmaxf(rintf(v[i].y * inv), -8.f), 7.f);
            float c = fminf(fmaxf(rintf(v[i].z * inv), -8.f), 7.f);
            float d = fminf(fmaxf(rintf(v[i].w * inv), -8.f), 7.f);
            // small integers are exact in bf16
            uint32_t ab = ((uint32_t)__bfloat16_as_ushort(__float2bfloat16(a)))
                        | ((uint32_t)__bfloat16_as_ushort(__float2bfloat16(b)) << 16);
            uint32_t cd = ((uint32_t)__bfloat16_as_ushort(__float2bfloat16(c)))
                        | ((uint32_t)__bfloat16_as_ushort(__float2bfloat16(d)) << 16);
            qo[tid + i * 256] = make_uint2(ab, cd);
        }
    }
}

// Kernel 2: ternarize weights -> bf16 {-1,0,+1}. grid 16384 x 256.
__global__ void k_wquant(const float* __restrict__ w) {
    float half = 0.5f * g_wscale;
    size_t base = (size_t)blockIdx.x * 1024 + threadIdx.x; // float4 units
    const float4* wp = reinterpret_cast<const float4*>(w);
    uint2* o = reinterpret_cast<uint2*>(g_wt);
#pragma unroll
    for (int i = 0; i < 4; i++) {
        size_t idx = base + (size_t)i * 256;
        float4 v = wp[idx];
        // ternary bf16 bits: +1 = 0x3F80, -1 = 0xBF80, 0 = 0
        uint32_t a = (v.x > half) ? 0x3F80u : ((v.x < -half) ? 0xBF80u : 0u);
        uint32_t b = (v.y > half) ? 0x3F80u : ((v.y < -half) ? 0xBF80u : 0u);
        uint32_t c = (v.z > half) ? 0x3F80u : ((v.z < -half) ? 0xBF80u : 0u);
        uint32_t d = (v.w > half) ? 0x3F80u : ((v.w < -half) ? 0xBF80u : 0u);
        o[idx] = make_uint2(a | (b << 16), c | (d << 16));
    }
}

// ============================================================================
// Kernel 3: bf16 HMMA GEMM — byte-identical inner loop to the measured best
// (tensor=83%). BM=128 x BN=128 x BK=64, 3-stage cp.async, 8 warps of 64x32,
// 2 CTAs per SM.
// ============================================================================
__device__ __forceinline__ void load_chunk(uint32_t stage, const __nv_bfloat16* Abase,
                                           const __nv_bfloat16* Bbase, int kc, int tid) {
    uint32_t a_s = stage;
    uint32_t b_s = stage + BM * ROWB;
    const char* ag = reinterpret_cast<const char*>(Abase) + kc * ROWB;
    const char* bg = reinterpret_cast<const char*>(Bbase) + kc * ROWB;
#pragma unroll
    for (int i = 0; i < 4; i++) {
        int g = tid + GTHREADS * i;
        int r = g >> 3, c = (g & 7) * 16;
        cp16(a_s + swz(r, c), ag + (size_t)r * K_BYTES + c);
    }
#pragma unroll
    for (int i = 0; i < 4; i++) {
        int g = tid + GTHREADS * i;
        int r = g >> 3, c = (g & 7) * 16;
        cp16(b_s + swz(r, c), bg + (size_t)r * K_BYTES + c);
    }
    cp_commit();
}

__global__ void __launch_bounds__(GTHREADS, 2) k_gemm(float* __restrict__ out) {
    extern __shared__ char smem[];
    uint32_t sb = smem_u32(smem);
    int tid = threadIdx.x;
    int wid = tid >> 5;
    int lane = tid & 31;

    // Grouped rasterization for L2 reuse
    const int num_pid_n = N_DIM / BN; // 128
    const int GROUP = 8;
    int pid = blockIdx.x;
    int npg = GROUP * num_pid_n;
    int group_id = pid / npg;
    int first_m = group_id * GROUP;
    int pid_m = first_m + ((pid % npg) % GROUP);
    int pid_n = (pid % npg) / GROUP;

    const __nv_bfloat16* Abase = g_xq + (size_t)pid_m * BM * K_DIM;
    const __nv_bfloat16* Bbase = g_wt + (size_t)pid_n * BN * K_DIM;

    int WM = (wid & 1) * 64;   // warp m offset (0 or 64)
    int WN = (wid >> 1) * 32;  // warp n offset (0,32,64,96)

    float acc[4][4][4];
#pragma unroll
    for (int i = 0; i < 4; i++)
#pragma unroll
        for (int j = 0; j < 4; j++)
#pragma unroll
            for (int q = 0; q < 4; q++) acc[i][j][q] = 0.f;

    // ldmatrix base offsets (k-step selects bits 5-6 by XOR)
    uint32_t a_off[4];
#pragma unroll
    for (int i = 0; i < 4; i++) {
        int row = WM + 16 * i + (lane & 15);
        a_off[i] = swz(row, ((lane >> 4) & 1) * 16);
    }
    uint32_t b_off[2];
#pragma unroll
    for (int p = 0; p < 2; p++) {
        int n = WN + 16 * p + (lane & 7) + ((lane >> 4) & 1) * 8;
        b_off[p] = (uint32_t)(BM * ROWB) + swz(n, ((lane >> 3) & 1) * 16);
    }

    // Prologue: fill 2 of 3 stages
    load_chunk(sb + 0 * STAGE_BYTES, Abase, Bbase, 0, tid);
    load_chunk(sb + 1 * STAGE_BYTES, Abase, Bbase, 1, tid);

    int slot = 0, lslot = 2;
#pragma unroll 1
    for (int kc = 0; kc < NKC; kc++) {
        if (kc < NKC - 1) cp_wait1(); else cp_wait0();
        __syncthreads();
        // Refill the slot freed last iteration
        if (kc + 2 < NKC) {
            load_chunk(sb + lslot * STAGE_BYTES, Abase, Bbase, kc + 2, tid);
            lslot++; if (lslot == STAGES) lslot = 0;
        }
        uint32_t stage = sb + slot * STAGE_BYTES;
        slot++; if (slot == STAGES) slot = 0;
#pragma unroll
        for (int ks = 0; ks < 4; ks++) {
            uint32_t kx = (uint32_t)(ks * 32);
            uint32_t ua[4][4], ub[2][4];
#pragma unroll
            for (int i = 0; i < 4; i++) ldm_x4(ua[i], stage + (a_off[i] ^ kx));
#pragma unroll
            for (int p = 0; p < 2; p++) ldm_x4(ub[p], stage + (b_off[p] ^ kx));
#pragma unroll
            for (int p = 0; p < 2; p++)
#pragma unroll
                for (int i = 0; i < 4; i++) {
                    hmma(acc[i][2 * p],     ua[i], ub[p]);
                    hmma(acc[i][2 * p + 1], ua[i], ub[p] + 2);
                }
        }
    }

    // Epilogue: scale by s[m]*wscale, streaming stores (evict-first)
    float ws = g_wscale;
#pragma unroll
    for (int i = 0; i < 4; i++) {
        int row0 = pid_m * BM + WM + 16 * i + (lane >> 2);
        float s0 = g_sx[row0] * ws;
        float s1 = g_sx[row0 + 8] * ws;
        float* r0 = out + (size_t)row0 * N_DIM + pid_n * BN + WN;
        float* r1 = r0 + (size_t)8 * N_DIM;
#pragma unroll
        for (int j = 0; j < 4; j++) {
            int col = 8 * j + 2 * (lane & 3);
            stg_cs_v2(r0 + col, acc[i][j][0] * s0, acc[i][j][1] * s0);
            stg_cs_v2(r1 + col, acc[i][j][2] * s1, acc[i][j][3] * s1);
        }
    }
}

// ============================================================================
// Launch
// ============================================================================
extern "C" void kernel_launch(void* const* d_in, const int* in_sizes, int n_in,
                              void* d_out, int out_size) {
    const float* x = (const float*)d_in[0];
    const float* w = (const float*)d_in[1];
    if (n_in >= 2 && in_sizes[0] == 67108864) { // defensive: identify by size
        w = (const float*)d_in[0];
        x = (const float*)d_in[1];
    }
    float* out = (float*)d_out;

    cudaFuncSetAttribute(k_gemm, cudaFuncAttributeMaxDynamicSharedMemorySize, GEMM_SMEM);

    // Fused: |w| mean (+final reduce) and independent x-quant in one kernel
    k_wabs_xq<<<WABS_BLOCKS + M_DIM, 256>>>(w, x);
    k_wquant<<<16384, 256>>>(w);
    k_gemm<<<(M_DIM / BM) * (N_DIM / BN), GTHREADS, GEMM_SMEM>>>(out);
}